// round 2
// baseline (speedup 1.0000x reference)
#include <cuda_runtime.h>
#include <cuda_bf16.h>
#include <cstdint>

// Problem constants
#define BATCH   64
#define SEQ     1024
#define IDIM    128
#define HDIM    512
#define G4      2048          // 4*HDIM
#define KTOT    640           // HDIM + IDIM  (fused [h, x] @ [U; W])
#define NGRP    4             // independent batch groups
#define GB      16            // batches per group   (M of recurrent GEMM)
#define NCTA    32            // CTAs per group
#define HC      16            // hidden units owned per CTA
#define NL      64            // local gate columns per CTA = 4*HC
#define THREADS 128
#define NKC     (KTOT / 16)   // 40 k-chunks of 16

// smem element strides (bf16 elems), padded so (stride/2) % 32 == 4 -> conflict-free frags
#define ZSTR 648
#define ASTR 648

// smem byte offsets
#define OFF_ZHI   0
#define OFF_ZLO   (OFF_ZHI + NL * ZSTR * 2)          // 82944
#define OFF_AHI   (OFF_ZLO + NL * ZSTR * 2)          // 165888
#define OFF_ALO   (OFF_AHI + GB * ASTR * 2)          // 186624
#define OFF_GATES (OFF_ALO + GB * ASTR * 2)          // 207360
#define OFF_C     (OFF_GATES + 4 * GB * HC * 4)      // 211456
#define OFF_BIAS  (OFF_C + GB * HC * 4)              // 212480
#define SMEM_SZ   (OFF_BIAS + NL * 4)                // 212736 bytes

// Global scratch (allowed: __device__ arrays, no allocation)
__device__ float g_h[2][BATCH][HDIM];   // ping-pong hidden state
__device__ int   g_cnt[NGRP];
__device__ int   g_gen[NGRP];

// -------- group barrier (sense-reversing, replay-safe: cnt returns to 0) ------
__device__ __forceinline__ int bar_sync(int grp, int my)
{
    __threadfence();
    if (atomicAdd(&g_cnt[grp], 1) == NCTA - 1) {
        atomicExch(&g_cnt[grp], 0);
        __threadfence();
        atomicAdd(&g_gen[grp], 1);
        __threadfence();
        return my + 1;
    }
    int v;
    do {
        asm volatile("ld.acquire.gpu.global.b32 %0, [%1];"
                     : "=r"(v) : "l"(&g_gen[grp]));
    } while (v == my);
    return v;
}

// -------- bf16 MMA m16n8k16 (f32 accum) --------------------------------------
__device__ __forceinline__ void mma_bf16(float* d, const unsigned* a, const unsigned* b)
{
    asm volatile(
        "mma.sync.aligned.m16n8k16.row.col.f32.bf16.bf16.f32 "
        "{%0,%1,%2,%3}, {%4,%5,%6,%7}, {%8,%9}, {%0,%1,%2,%3};\n"
        : "+f"(d[0]), "+f"(d[1]), "+f"(d[2]), "+f"(d[3])
        : "r"(a[0]), "r"(a[1]), "r"(a[2]), "r"(a[3]), "r"(b[0]), "r"(b[1]));
}

__device__ __forceinline__ float fast_sigmoid(float x) { return 1.f / (1.f + __expf(-x)); }
__device__ __forceinline__ float fast_tanh(float x)    { return 1.f - 2.f / (__expf(2.f * x) + 1.f); }

// ==============================================================================
// Persistent recurrent kernel: 4 groups x 32 CTAs, weights SMEM-resident,
// bf16 hi/lo 3-pass tensor-core GEMM per step, fp32 state.
// ==============================================================================
extern "C" __global__ void __launch_bounds__(THREADS, 1)
lstm_persistent_kernel(const float* __restrict__ x,
                       const float* __restrict__ W,
                       const float* __restrict__ U,
                       const float* __restrict__ bias)
{
    extern __shared__ char smem[];
    __nv_bfloat16* zhi  = (__nv_bfloat16*)(smem + OFF_ZHI);
    __nv_bfloat16* zlo  = (__nv_bfloat16*)(smem + OFF_ZLO);
    __nv_bfloat16* ahi  = (__nv_bfloat16*)(smem + OFF_AHI);
    __nv_bfloat16* alo  = (__nv_bfloat16*)(smem + OFF_ALO);
    float*         gat  = (float*)(smem + OFF_GATES);   // [4][GB][HC]
    float*         cmem = (float*)(smem + OFF_C);       // [GB][HC]
    float*         bs   = (float*)(smem + OFF_BIAS);    // [NL]

    const int tid  = threadIdx.x;
    const int lane = tid & 31;
    const int warp = tid >> 5;            // warp == gate index (0..3)
    const int grp  = blockIdx.x >> 5;     // 0..3
    const int gc   = blockIdx.x & 31;     // hidden-slice id within group
    const int b0   = grp * GB;            // first batch of this group
    const int h0   = gc * HC;             // first hidden unit owned

    // ---------------- prologue: load Z = [U; W] column slice, split hi/lo ------
    for (int idx = tid; idx < KTOT * NL; idx += THREADS) {
        int k  = idx >> 6;
        int nl = idx & 63;
        int g  = nl >> 4, hid = nl & 15;
        int col = g * HDIM + h0 + hid;
        float v = (k < HDIM) ? U[(size_t)k * G4 + col]
                             : W[(size_t)(k - HDIM) * G4 + col];
        __nv_bfloat16 hi = __float2bfloat16(v);
        float lo = v - __bfloat162float(hi);
        zhi[nl * ZSTR + k] = hi;
        zlo[nl * ZSTR + k] = __float2bfloat16(lo);
    }
    if (tid < NL) {
        int g = tid >> 4, hid = tid & 15;
        bs[tid] = bias[g * HDIM + h0 + hid];
    }
    for (int idx = tid; idx < GB * HC; idx += THREADS) {
        cmem[idx] = 0.f;
        int b = idx >> 4, hid = idx & 15;
        g_h[0][b0 + b][h0 + hid] = 0.f;   // zero initial hidden state slice
    }
    __threadfence();
    __syncthreads();
    int mygen = 0;
    if (tid == 0) {
        asm volatile("ld.acquire.gpu.global.b32 %0, [%1];"
                     : "=r"(mygen) : "l"(&g_gen[grp]));
        mygen = bar_sync(grp, mygen);
    }
    __syncthreads();

    const int r  = lane >> 2;           // fragment row (0..7)
    const int cq = (lane & 3) * 2;      // fragment col pair base

    // ---------------- time loop ------------------------------------------------
    for (int s = 0; s < SEQ; s++) {
        const int par = s & 1;

        // ---- stage A = [h | x_s] as bf16 hi/lo into smem ----
        const float* hsrc = &g_h[par][b0][0];
        for (int idx = tid; idx < GB * HDIM / 2; idx += THREADS) {   // 4096 pairs
            int b = idx >> 8, kp = idx & 255;
            float2 v = *(const float2*)(hsrc + b * HDIM + kp * 2);
            __nv_bfloat162 h2, l2;
            h2.x = __float2bfloat16(v.x);
            h2.y = __float2bfloat16(v.y);
            l2.x = __float2bfloat16(v.x - __bfloat162float(h2.x));
            l2.y = __float2bfloat16(v.y - __bfloat162float(h2.y));
            *(__nv_bfloat162*)(ahi + b * ASTR + kp * 2) = h2;
            *(__nv_bfloat162*)(alo + b * ASTR + kp * 2) = l2;
        }
        for (int idx = tid; idx < GB * IDIM / 2; idx += THREADS) {   // 1024 pairs
            int b = idx >> 6, ip = idx & 63;
            float2 v = *(const float2*)(x + ((size_t)(b0 + b) * SEQ + s) * IDIM + ip * 2);
            __nv_bfloat162 h2, l2;
            h2.x = __float2bfloat16(v.x);
            h2.y = __float2bfloat16(v.y);
            l2.x = __float2bfloat16(v.x - __bfloat162float(h2.x));
            l2.y = __float2bfloat16(v.y - __bfloat162float(h2.y));
            *(__nv_bfloat162*)(ahi + b * ASTR + HDIM + ip * 2) = h2;
            *(__nv_bfloat162*)(alo + b * ASTR + HDIM + ip * 2) = l2;
        }
        __syncthreads();

        // ---- GEMM: gates(16x64) += A(16x640) @ Z(640x64), 3-pass hi/lo ----
        float acc[2][4];
        #pragma unroll
        for (int t = 0; t < 2; t++)
            #pragma unroll
            for (int j = 0; j < 4; j++) acc[t][j] = 0.f;

        #pragma unroll 2
        for (int kc = 0; kc < NKC; kc++) {
            const int k0 = kc * 16;
            unsigned a_h[4], a_l[4];
            a_h[0] = *(const unsigned*)(ahi + r * ASTR + k0 + cq);
            a_h[1] = *(const unsigned*)(ahi + (r + 8) * ASTR + k0 + cq);
            a_h[2] = *(const unsigned*)(ahi + r * ASTR + k0 + cq + 8);
            a_h[3] = *(const unsigned*)(ahi + (r + 8) * ASTR + k0 + cq + 8);
            a_l[0] = *(const unsigned*)(alo + r * ASTR + k0 + cq);
            a_l[1] = *(const unsigned*)(alo + (r + 8) * ASTR + k0 + cq);
            a_l[2] = *(const unsigned*)(alo + r * ASTR + k0 + cq + 8);
            a_l[3] = *(const unsigned*)(alo + (r + 8) * ASTR + k0 + cq + 8);
            #pragma unroll
            for (int t = 0; t < 2; t++) {
                const int n = warp * 16 + t * 8 + r;
                unsigned b_h[2], b_l[2];
                b_h[0] = *(const unsigned*)(zhi + n * ZSTR + k0 + cq);
                b_h[1] = *(const unsigned*)(zhi + n * ZSTR + k0 + 8 + cq);
                b_l[0] = *(const unsigned*)(zlo + n * ZSTR + k0 + cq);
                b_l[1] = *(const unsigned*)(zlo + n * ZSTR + k0 + 8 + cq);
                mma_bf16(acc[t], a_h, b_h);   // hi*hi
                mma_bf16(acc[t], a_l, b_h);   // lo*hi
                mma_bf16(acc[t], a_h, b_l);   // hi*lo
            }
        }

        // ---- write gate accumulators to smem ----
        #pragma unroll
        for (int t = 0; t < 2; t++) {
            const int cb = t * 8 + cq;
            gat[warp * 256 + r * 16 + cb]           = acc[t][0];
            gat[warp * 256 + r * 16 + cb + 1]       = acc[t][1];
            gat[warp * 256 + (r + 8) * 16 + cb]     = acc[t][2];
            gat[warp * 256 + (r + 8) * 16 + cb + 1] = acc[t][3];
        }
        __syncthreads();

        // ---- elementwise LSTM cell update (256 elems over 128 threads) ----
        const int npar = (s + 1) & 1;
        #pragma unroll
        for (int e = 0; e < 2; e++) {
            int idx = tid + e * THREADS;
            int b = idx >> 4, hid = idx & 15;
            float gi = gat[0 * 256 + b * 16 + hid] + bs[0 * 16 + hid];
            float gf = gat[1 * 256 + b * 16 + hid] + bs[1 * 16 + hid];
            float gg = gat[2 * 256 + b * 16 + hid] + bs[2 * 16 + hid];
            float go = gat[3 * 256 + b * 16 + hid] + bs[3 * 16 + hid];
            float i_ = fast_sigmoid(gi);
            float f_ = fast_sigmoid(gf);
            float g_ = fast_tanh(gg);
            float o_ = fast_sigmoid(go);
            float c  = f_ * cmem[idx] + i_ * g_;
            cmem[idx] = c;
            g_h[npar][b0 + b][h0 + hid] = o_ * fast_tanh(c);
        }
        __threadfence();
        __syncthreads();
        if (tid == 0) mygen = bar_sync(grp, mygen);
        __syncthreads();
    }
}

// ==============================================================================
// Final FC head: out[b, o] = h_last[b] . fc_w[:, o] + fc_b[o]
// h_last lives in g_h[SEQ & 1] == g_h[0]
// ==============================================================================
extern "C" __global__ void fc_kernel(const float* __restrict__ fc_w,
                                     const float* __restrict__ fc_b,
                                     float* __restrict__ out)
{
    const int b    = blockIdx.x;
    const int warp = threadIdx.x >> 5;   // output index 0..6
    const int lane = threadIdx.x & 31;
    float acc = 0.f;
    for (int k = lane; k < HDIM; k += 32)
        acc += g_h[0][b][k] * fc_w[k * 7 + warp];
    #pragma unroll
    for (int o = 16; o > 0; o >>= 1)
        acc += __shfl_down_sync(0xffffffffu, acc, o);
    if (lane == 0) out[b * 7 + warp] = acc + fc_b[warp];
}

// ==============================================================================
extern "C" void kernel_launch(void* const* d_in, const int* in_sizes, int n_in,
                              void* d_out, int out_size)
{
    (void)in_sizes; (void)n_in; (void)out_size;
    const float* x    = (const float*)d_in[0];
    const float* W    = (const float*)d_in[1];
    const float* U    = (const float*)d_in[2];
    const float* bias = (const float*)d_in[3];
    const float* fc_w = (const float*)d_in[4];
    const float* fc_b = (const float*)d_in[5];

    cudaFuncSetAttribute(lstm_persistent_kernel,
                         cudaFuncAttributeMaxDynamicSharedMemorySize, SMEM_SZ);
    lstm_persistent_kernel<<<NGRP * NCTA, THREADS, SMEM_SZ>>>(x, W, U, bias);
    fc_kernel<<<BATCH, 224>>>(fc_w, fc_b, (float*)d_out);
}

// round 3
// speedup vs baseline: 2.0494x; 2.0494x over previous
#include <cuda_runtime.h>
#include <cuda_fp16.h>
#include <cstdint>

#define BATCH   64
#define SEQ     1024
#define IDIM    128
#define HDIM    512
#define G4      2048
#define KTOT    640
#define NGRP    4
#define GB      16
#define NCTA    32
#define HC      16
#define NL      64
#define THREADS 128
#define NCH_H   32
#define NCH_X   8

#define ZSTR 648
#define ASTR 648
#define OFF_Z   0
#define OFF_AH  (NL * ZSTR * 2)
#define OFF_AL  (OFF_AH + GB * ASTR * 2)
#define SMEM_SZ (OFF_AL + GB * ASTR * 2)

__device__ __half g_xhi[BATCH * SEQ * IDIM];
__device__ __half g_xlo[BATCH * SEQ * IDIM];
__device__ __half g_hhi[2][BATCH][HDIM];
__device__ __half g_hlo[2][BATCH][HDIM];
__device__ int    g_flag[NGRP][NCTA][32];
__device__ int    g_cnt;
__device__ int    g_gen;

__device__ __forceinline__ void bar_all(int n)
{
    int my;
    asm volatile("ld.acquire.gpu.global.b32 %0, [%1];" : "=r"(my) : "l"(&g_gen));
    __threadfence();
    if (atomicAdd(&g_cnt, 1) == n - 1) {
        atomicExch(&g_cnt, 0);
        __threadfence();
        atomicAdd(&g_gen, 1);
    } else {
        int v;
        do { asm volatile("ld.acquire.gpu.global.b32 %0, [%1];" : "=r"(v) : "l"(&g_gen)); }
        while (v == my);
    }
}

__device__ __forceinline__ void poll_flags(int grp, int lane, int need)
{
    const int* fp = &g_flag[grp][lane][0];
    int v;
    do { asm volatile("ld.acquire.gpu.global.b32 %0, [%1];" : "=r"(v) : "l"(fp)); }
    while (__any_sync(0xffffffffu, v < need));
}

__device__ __forceinline__ void ldsm4(unsigned r[4], uint32_t a)
{
    asm volatile("ldmatrix.sync.aligned.m8n8.x4.shared.b16 {%0,%1,%2,%3}, [%4];"
                 : "=r"(r[0]), "=r"(r[1]), "=r"(r[2]), "=r"(r[3]) : "r"(a));
}
__device__ __forceinline__ void mma_f16(float* d, const unsigned* a, const unsigned* b)
{
    asm volatile(
        "mma.sync.aligned.m16n8k16.row.col.f32.f16.f16.f32 "
        "{%0,%1,%2,%3}, {%4,%5,%6,%7}, {%8,%9}, {%0,%1,%2,%3};\n"
        : "+f"(d[0]), "+f"(d[1]), "+f"(d[2]), "+f"(d[3])
        : "r"(a[0]), "r"(a[1]), "r"(a[2]), "r"(a[3]), "r"(b[0]), "r"(b[1]));
}

__device__ __forceinline__ float fsig(float x)  { return 1.f / (1.f + __expf(-x)); }
__device__ __forceinline__ float ftanh(float x) { return 1.f - 2.f / (__expf(2.f * x) + 1.f); }

// ---------------- x pre-split: fp32 -> fp16 hi/lo -----------------------------
extern "C" __global__ void xsplit_kernel(const float* __restrict__ x)
{
    int idx = (blockIdx.x * 256 + threadIdx.x) * 4;
    float4 v = *(const float4*)(x + idx);
    __half h0 = __float2half(v.x), h1 = __float2half(v.y),
           h2 = __float2half(v.z), h3 = __float2half(v.w);
    *(__half2*)(g_xhi + idx)     = __halves2half2(h0, h1);
    *(__half2*)(g_xhi + idx + 2) = __halves2half2(h2, h3);
    *(__half2*)(g_xlo + idx)     = __halves2half2(__float2half(v.x - __half2float(h0)),
                                                  __float2half(v.y - __half2float(h1)));
    *(__half2*)(g_xlo + idx + 2) = __halves2half2(__float2half(v.z - __half2float(h2)),
                                                  __float2half(v.w - __half2float(h3)));
}

// ---------------- persistent LSTM ---------------------------------------------
extern "C" __global__ void __launch_bounds__(THREADS, 1)
lstm_kernel(const float* __restrict__ W, const float* __restrict__ U,
            const float* __restrict__ bias,
            const float* __restrict__ fc_w, const float* __restrict__ fc_b,
            float* __restrict__ out)
{
    extern __shared__ char smem[];
    __half* zh = (__half*)(smem + OFF_Z);

    const int tid  = threadIdx.x;
    const int lane = tid & 31;
    const int warp = tid >> 5;
    const int grp  = blockIdx.x >> 5;
    const int gc   = blockIdx.x & 31;
    const int b0   = grp * GB;
    const int h0   = gc * HC;
    const uint32_t smb = (uint32_t)__cvta_generic_to_shared(smem);

    // weights, gate-interleaved local cols: nl -> hid=nl>>2, gate=nl&3
    for (int idx = tid; idx < KTOT * NL; idx += THREADS) {
        int k = idx >> 6, nl = idx & 63;
        int col = (nl & 3) * HDIM + h0 + (nl >> 2);
        float v = (k < HDIM) ? U[(size_t)k * G4 + col]
                             : W[(size_t)(k - HDIM) * G4 + col];
        zh[nl * ZSTR + k] = __float2half(v);
    }
    const int q = (lane >> 1) & 1;
    float bI[2], bF[2], bG[2], bO[2];
    #pragma unroll
    for (int t = 0; t < 2; t++) {
        int ht = h0 + warp * 4 + t * 2 + q;
        bI[t] = bias[ht];            bF[t] = bias[HDIM + ht];
        bG[t] = bias[2 * HDIM + ht]; bO[t] = bias[3 * HDIM + ht];
    }
    // stage x_0
    #pragma unroll
    for (int j = 0; j < 2; j++) {
        int i = tid + j * THREADS;
        int b = i >> 4, c8 = i & 15;
        size_t src = ((size_t)(b0 + b) * SEQ) * IDIM + c8 * 8;
        *(uint4*)(smem + OFF_AH + (b * ASTR + HDIM + c8 * 8) * 2) = *(const uint4*)(g_xhi + src);
        *(uint4*)(smem + OFF_AL + (b * ASTR + HDIM + c8 * 8) * 2) = *(const uint4*)(g_xlo + src);
    }
    if (tid == 0) g_flag[grp][gc][0] = 0;
    __syncthreads();
    if (tid == 0) bar_all(NGRP * NCTA);
    __syncthreads();

    // ldmatrix lane addresses
    const uint32_t aHiA = smb + OFF_AH + (((lane & 15) * ASTR + ((lane >> 4) << 3)) << 1);
    const uint32_t aLoA = smb + OFF_AL + (((lane & 15) * ASTR + ((lane >> 4) << 3)) << 1);
    const int brow = warp * 16 + ((lane & 7) | ((lane >> 1) & 8));
    const uint32_t bHiA = smb + OFF_Z + ((brow * ZSTR + (lane & 8)) << 1);

    const int r = lane >> 2;
    float c0 = 0.f, c1 = 0.f;

    for (int s = 0; s < SEQ; s++) {
        float acc[2][4] = {{0.f,0.f,0.f,0.f},{0.f,0.f,0.f,0.f}};

        // x-part GEMM (h-independent)
        #pragma unroll
        for (int kc = NCH_H; kc < NCH_H + NCH_X; kc++) {
            unsigned ah[4], al[4], bh[4];
            ldsm4(ah, aHiA + kc * 32);
            ldsm4(al, aLoA + kc * 32);
            ldsm4(bh, bHiA + kc * 32);
            mma_f16(acc[0], ah, bh);
            mma_f16(acc[0], al, bh);
            mma_f16(acc[1], ah, bh + 2);
            mma_f16(acc[1], al, bh + 2);
        }

        if (s > 0 && warp == 0) poll_flags(grp, lane, s);
        __syncthreads();

        // stage h_s and x_{s+1}
        if (s > 0) {
            const __half* hs = &g_hhi[s & 1][b0][0];
            const __half* ls = &g_hlo[s & 1][b0][0];
            #pragma unroll
            for (int j = 0; j < 8; j++) {
                int i = tid + j * THREADS;
                int b = i >> 6, c8 = i & 63;
                *(uint4*)(smem + OFF_AH + (b * ASTR + c8 * 8) * 2) = *(const uint4*)(hs + b * HDIM + c8 * 8);
                *(uint4*)(smem + OFF_AL + (b * ASTR + c8 * 8) * 2) = *(const uint4*)(ls + b * HDIM + c8 * 8);
            }
        }
        if (s + 1 < SEQ) {
            #pragma unroll
            for (int j = 0; j < 2; j++) {
                int i = tid + j * THREADS;
                int b = i >> 4, c8 = i & 15;
                size_t src = ((size_t)(b0 + b) * SEQ + (s + 1)) * IDIM + c8 * 8;
                *(uint4*)(smem + OFF_AH + (b * ASTR + HDIM + c8 * 8) * 2) = *(const uint4*)(g_xhi + src);
                *(uint4*)(smem + OFF_AL + (b * ASTR + HDIM + c8 * 8) * 2) = *(const uint4*)(g_xlo + src);
            }
        }
        __syncthreads();

        // h-part GEMM
        if (s > 0) {
            #pragma unroll 8
            for (int kc = 0; kc < NCH_H; kc++) {
                unsigned ah[4], al[4], bh[4];
                ldsm4(ah, aHiA + kc * 32);
                ldsm4(al, aLoA + kc * 32);
                ldsm4(bh, bHiA + kc * 32);
                mma_f16(acc[0], ah, bh);
                mma_f16(acc[0], al, bh);
                mma_f16(acc[1], ah, bh + 2);
                mma_f16(acc[1], al, bh + 2);
            }
        }

        // register epilogue: pair exchange via shfl.xor 1
        const int np = (s + 1) & 1;
        #pragma unroll
        for (int t = 0; t < 2; t++) {
            float e0 = __shfl_xor_sync(0xffffffffu, acc[t][0], 1);
            float e1 = __shfl_xor_sync(0xffffffffu, acc[t][1], 1);
            float e2 = __shfl_xor_sync(0xffffffffu, acc[t][2], 1);
            float e3 = __shfl_xor_sync(0xffffffffu, acc[t][3], 1);
            float gi, gf, gg, go;
            int bidx;
            if ((lane & 1) == 0) {   // row r: own (i,f), partner's (g,o)
                gi = acc[t][0] + bI[t]; gf = acc[t][1] + bF[t];
                gg = e0 + bG[t];        go = e1 + bO[t];
                bidx = r;
            } else {                 // row r+8: partner's (i,f), own (g,o)
                gi = e2 + bI[t];        gf = e3 + bF[t];
                gg = acc[t][2] + bG[t]; go = acc[t][3] + bO[t];
                bidx = r + 8;
            }
            float i_ = fsig(gi), f_ = fsig(gf), g_ = ftanh(gg), o_ = fsig(go);
            float& cc = t ? c1 : c0;
            cc = f_ * cc + i_ * g_;
            float h = o_ * ftanh(cc);
            int ht = h0 + warp * 4 + t * 2 + q;
            __half hh = __float2half(h);
            g_hhi[np][b0 + bidx][ht] = hh;
            g_hlo[np][b0 + bidx][ht] = __float2half(h - __half2float(hh));
        }
        __syncthreads();
        if (tid == 0) {
            int nf = s + 1;
            asm volatile("st.release.gpu.global.b32 [%0], %1;"
                         :: "l"(&g_flag[grp][gc][0]), "r"(nf));
        }
    }

    // FC head: one CTA per group
    if (gc == 0) {
        if (warp == 0) poll_flags(grp, lane, SEQ);
        __syncthreads();
        int b = tid >> 3, l8 = tid & 7;
        float a7[7] = {0.f,0.f,0.f,0.f,0.f,0.f,0.f};
        for (int it = 0; it < HDIM / 8; it++) {
            int k = l8 + it * 8;
            float hv = __half2float(g_hhi[0][b0 + b][k]) + __half2float(g_hlo[0][b0 + b][k]);
            #pragma unroll
            for (int o = 0; o < 7; o++) a7[o] += hv * fc_w[k * 7 + o];
        }
        #pragma unroll
        for (int o = 0; o < 7; o++) {
            a7[o] += __shfl_xor_sync(0xffffffffu, a7[o], 4);
            a7[o] += __shfl_xor_sync(0xffffffffu, a7[o], 2);
            a7[o] += __shfl_xor_sync(0xffffffffu, a7[o], 1);
        }
        if (l8 == 0)
            #pragma unroll
            for (int o = 0; o < 7; o++) out[(b0 + b) * 7 + o] = a7[o] + fc_b[o];
    }
}

extern "C" void kernel_launch(void* const* d_in, const int* in_sizes, int n_in,
                              void* d_out, int out_size)
{
    (void)in_sizes; (void)n_in; (void)out_size;
    const float* x    = (const float*)d_in[0];
    const float* W    = (const float*)d_in[1];
    const float* U    = (const float*)d_in[2];
    const float* bias = (const float*)d_in[3];
    const float* fc_w = (const float*)d_in[4];
    const float* fc_b = (const float*)d_in[5];

    cudaFuncSetAttribute(lstm_kernel,
                         cudaFuncAttributeMaxDynamicSharedMemorySize, SMEM_SZ);
    xsplit_kernel<<<BATCH * SEQ * IDIM / 1024, 256>>>(x);
    lstm_kernel<<<NGRP * NCTA, THREADS, SMEM_SZ>>>(W, U, bias, fc_w, fc_b, (float*)d_out);
}